// round 16
// baseline (speedup 1.0000x reference)
#include <cuda_runtime.h>
#include <cuda_fp16.h>

#define NN 50000
#define NE 1600000
#define PAD 128
#define L2E 1.4426950408889634f

// ---------------- scratch (device globals; zero-initialized at load) ----------
__device__ __align__(16) __half g_xh[NN * 128];
__device__ float g_al[NN * 8];
__device__ float g_ar[NN * 8];
__device__ int   g_cnt[NN];          // zeroed at load; reset at TAIL of k_agg
__device__ __align__(16) int2 g_cs[NN * PAD];   // (src, w*log2e bits)

// ---------------- edge scatter (standalone; proven R5 shape) -------------------
__global__ void k_scatter(const int* __restrict__ src, const int* __restrict__ dst,
                          const float* __restrict__ w, int e) {
    int i0 = (blockIdx.x * blockDim.x + threadIdx.x) * 4;
    if (i0 + 4 <= e) {
        int4   s4 = *(const int4*)&src[i0];
        int4   d4 = *(const int4*)&dst[i0];
        float4 w4 = *(const float4*)&w[i0];
        w4.x *= L2E; w4.y *= L2E; w4.z *= L2E; w4.w *= L2E;
        int p0 = atomicAdd(&g_cnt[d4.x], 1);
        int p1 = atomicAdd(&g_cnt[d4.y], 1);
        int p2 = atomicAdd(&g_cnt[d4.z], 1);
        int p3 = atomicAdd(&g_cnt[d4.w], 1);
        p0 = min(p0, PAD - 1); p1 = min(p1, PAD - 1);
        p2 = min(p2, PAD - 1); p3 = min(p3, PAD - 1);
        g_cs[d4.x * PAD + p0] = make_int2(s4.x, __float_as_int(w4.x));
        g_cs[d4.y * PAD + p1] = make_int2(s4.y, __float_as_int(w4.y));
        g_cs[d4.z * PAD + p2] = make_int2(s4.z, __float_as_int(w4.z));
        g_cs[d4.w * PAD + p3] = make_int2(s4.w, __float_as_int(w4.w));
    } else {
        for (int i = i0; i < e; i++) {
            int d = dst[i];
            int p = min(atomicAdd(&g_cnt[d], 1), PAD - 1);
            g_cs[d * PAD + p] = make_int2(src[i], __float_as_int(w[i] * L2E));
        }
    }
}

// ---------------- tf32 tensor-core GEMM (+ al/ar epilogue) ---------------------
#define SF 132
#define SW 136
#define GEMM_SMEM_BYTES ((128 * SF + 128 * SW) * 4)

__device__ __forceinline__ unsigned f2tf32(float f) {
    unsigned u;
    asm("cvt.rna.tf32.f32 %0, %1;" : "=r"(u) : "f"(f));
    return u;
}

__global__ void __launch_bounds__(256) k_gemm(
    const float* __restrict__ feat, const float* __restrict__ Wlin,
    const float* __restrict__ Wres, const float* __restrict__ attl,
    const float* __restrict__ attr, float* __restrict__ dres, int n) {
    int bx = blockIdx.x >> 1;
    int by = blockIdx.x & 1;          // 0 -> x/g_xh (+al/ar), 1 -> residual
    extern __shared__ float sm[];
    float* sF = sm;
    float* sW = sm + 128 * SF;
    int tid = threadIdx.x;
    const float* W = by ? Wres : Wlin;
    int node0 = bx * 128;

#pragma unroll
    for (int t = 0; t < 16; t++) {
        int i = tid + t * 256;
        int r = i >> 5;
        int c4 = i & 31;
        float4 v = ((const float4*)W)[i];
        uint4 u = make_uint4(f2tf32(v.x), f2tf32(v.y), f2tf32(v.z), f2tf32(v.w));
        *(uint4*)&sW[r * SW + c4 * 4] = u;
    }
#pragma unroll
    for (int t = 0; t < 16; t++) {
        int i = tid + t * 256;
        int r = i >> 5;
        int c4 = i & 31;
        int gn = node0 + r;
        float4 v = make_float4(0.f, 0.f, 0.f, 0.f);
        if (gn < n) v = ((const float4*)feat)[gn * 32 + c4];
        uint4 u = make_uint4(f2tf32(v.x), f2tf32(v.y), f2tf32(v.z), f2tf32(v.w));
        *(uint4*)&sF[r * SF + c4 * 4] = u;
    }
    __syncthreads();

    int w = tid >> 5, lane = tid & 31;
    int wm = (w >> 2) * 64;
    int wn = (w & 3) * 32;
    int gid = lane >> 2, tig = lane & 3;

    float c[4][4][4];
#pragma unroll
    for (int mi = 0; mi < 4; mi++)
#pragma unroll
        for (int ni = 0; ni < 4; ni++)
#pragma unroll
            for (int q = 0; q < 4; q++) c[mi][ni][q] = 0.f;

    const unsigned* uF = (const unsigned*)sF;
    const unsigned* uW = (const unsigned*)sW;

#pragma unroll
    for (int ks = 0; ks < 16; ks++) {
        int k0 = ks * 8;
        unsigned a[4][4], b[4][2];
#pragma unroll
        for (int mi = 0; mi < 4; mi++) {
            int r = wm + mi * 16 + gid;
            a[mi][0] = uF[r * SF + k0 + tig];
            a[mi][1] = uF[(r + 8) * SF + k0 + tig];
            a[mi][2] = uF[r * SF + k0 + tig + 4];
            a[mi][3] = uF[(r + 8) * SF + k0 + tig + 4];
        }
#pragma unroll
        for (int ni = 0; ni < 4; ni++) {
            int cb = wn + ni * 8 + gid;
            b[ni][0] = uW[(k0 + tig) * SW + cb];
            b[ni][1] = uW[(k0 + tig + 4) * SW + cb];
        }
#pragma unroll
        for (int mi = 0; mi < 4; mi++)
#pragma unroll
            for (int ni = 0; ni < 4; ni++)
                asm volatile(
                    "mma.sync.aligned.m16n8k8.row.col.f32.tf32.tf32.f32 "
                    "{%0,%1,%2,%3}, {%4,%5,%6,%7}, {%8,%9}, {%0,%1,%2,%3};"
                    : "+f"(c[mi][ni][0]), "+f"(c[mi][ni][1]),
                      "+f"(c[mi][ni][2]), "+f"(c[mi][ni][3])
                    : "r"(a[mi][0]), "r"(a[mi][1]), "r"(a[mi][2]), "r"(a[mi][3]),
                      "r"(b[ni][0]), "r"(b[ni][1]));
    }

    if (by) {
#pragma unroll
        for (int mi = 0; mi < 4; mi++) {
            int row = node0 + wm + mi * 16 + gid;
#pragma unroll
            for (int ni = 0; ni < 4; ni++) {
                int col = wn + ni * 8 + tig * 2;
                if (row < n)
                    *(float2*)&dres[row * 128 + col] =
                        make_float2(c[mi][ni][0], c[mi][ni][1]);
                if (row + 8 < n)
                    *(float2*)&dres[(row + 8) * 128 + col] =
                        make_float2(c[mi][ni][2], c[mi][ni][3]);
            }
        }
    } else {
#pragma unroll
        for (int mi = 0; mi < 4; mi++) {
            int row = node0 + wm + mi * 16 + gid;
#pragma unroll
            for (int ni = 0; ni < 4; ni++) {
                int col = wn + ni * 8 + tig * 2;
                if (row < n) {
                    __half2 hh = __floats2half2_rn(c[mi][ni][0], c[mi][ni][1]);
                    *(__half2*)&g_xh[row * 128 + col] = hh;
                }
                if (row + 8 < n) {
                    __half2 hh = __floats2half2_rn(c[mi][ni][2], c[mi][ni][3]);
                    *(__half2*)&g_xh[(row + 8) * 128 + col] = hh;
                }
            }
        }
        float2 alv[4], arv[4];
#pragma unroll
        for (int ni = 0; ni < 4; ni++) {
            int col = wn + ni * 8 + tig * 2;
            alv[ni] = *(const float2*)&attl[col];
            arv[ni] = *(const float2*)&attr[col];
        }
        int h_lo = wn >> 4;
#pragma unroll
        for (int mi = 0; mi < 4; mi++) {
            int row = node0 + wm + mi * 16 + gid;
            float v[8];
#pragma unroll
            for (int q = 0; q < 8; q++) v[q] = 0.f;
#pragma unroll
            for (int ni = 0; ni < 2; ni++) {
                v[0] += c[mi][ni][0] * alv[ni].x + c[mi][ni][1] * alv[ni].y;
                v[1] += c[mi][ni][0] * arv[ni].x + c[mi][ni][1] * arv[ni].y;
                v[4] += c[mi][ni][2] * alv[ni].x + c[mi][ni][3] * alv[ni].y;
                v[5] += c[mi][ni][2] * arv[ni].x + c[mi][ni][3] * arv[ni].y;
            }
#pragma unroll
            for (int ni = 2; ni < 4; ni++) {
                v[2] += c[mi][ni][0] * alv[ni].x + c[mi][ni][1] * alv[ni].y;
                v[3] += c[mi][ni][0] * arv[ni].x + c[mi][ni][1] * arv[ni].y;
                v[6] += c[mi][ni][2] * alv[ni].x + c[mi][ni][3] * alv[ni].y;
                v[7] += c[mi][ni][2] * arv[ni].x + c[mi][ni][3] * arv[ni].y;
            }
#pragma unroll
            for (int q = 0; q < 8; q++) {
                v[q] += __shfl_xor_sync(0xffffffffu, v[q], 1);
                v[q] += __shfl_xor_sync(0xffffffffu, v[q], 2);
            }
            if (tig == 0) {
                if (row < n) {
                    g_al[row * 8 + h_lo] = v[0];
                    g_ar[row * 8 + h_lo] = v[1];
                    g_al[row * 8 + h_lo + 1] = v[2];
                    g_ar[row * 8 + h_lo + 1] = v[3];
                }
                if (row + 8 < n) {
                    g_al[(row + 8) * 8 + h_lo] = v[4];
                    g_ar[(row + 8) * 8 + h_lo] = v[5];
                    g_al[(row + 8) * 8 + h_lo + 1] = v[6];
                    g_ar[(row + 8) * 8 + h_lo + 1] = v[7];
                }
            }
        }
    }
}

// ---------------- fused softmax + message passing (exact R15 kernel) -----------
// Quarter-warp per edge: lane = (ql = lane>>3, li = lane&7 = head & col group).
// No stores/shuffles inside the gather loop; reductions post-loop;
// terminal-only g_cnt reset (R12-proven).
__global__ void k_agg(float* __restrict__ out, int n) {
    int wid = (blockIdx.x * blockDim.x + threadIdx.x) >> 5;
    int lane = threadIdx.x & 31;
    if (wid >= n) return;
    int cnt0 = min(g_cnt[wid], PAD);
    int beg = wid * PAD;
    int end = beg + cnt0;

    int li = lane & 7;
    int ql = lane >> 3;
    float arn = g_ar[wid * 8 + li];

    float denom = 0.f;
    float a[16];
#pragma unroll
    for (int k = 0; k < 16; k++) a[k] = 0.f;

    int e = beg;
    for (; e + 8 <= end; e += 8) {
        int2 c[2];
#pragma unroll
        for (int j = 0; j < 2; j++) c[j] = g_cs[e + 4 * j + ql];
        float l[2];
#pragma unroll
        for (int j = 0; j < 2; j++) l[j] = g_al[c[j].x * 8 + li];
        uint4 x0[2], x1[2];
#pragma unroll
        for (int j = 0; j < 2; j++) {
            x0[j] = *(const uint4*)&g_xh[c[j].x * 128 + li * 16];
            x1[j] = *(const uint4*)&g_xh[c[j].x * 128 + li * 16 + 8];
        }
#pragma unroll
        for (int j = 0; j < 2; j++) {
            float aa = (l[j] + arn) * __int_as_float(c[j].y);
            aa = (aa > 0.f) ? aa : 0.2f * aa;
            float p = exp2f(fminf(aa, 100.f));
            denom += p;
            float2 f;
            f = __half22float2(*(__half2*)&x0[j].x); a[0] += p * f.x; a[1] += p * f.y;
            f = __half22float2(*(__half2*)&x0[j].y); a[2] += p * f.x; a[3] += p * f.y;
            f = __half22float2(*(__half2*)&x0[j].z); a[4] += p * f.x; a[5] += p * f.y;
            f = __half22float2(*(__half2*)&x0[j].w); a[6] += p * f.x; a[7] += p * f.y;
            f = __half22float2(*(__half2*)&x1[j].x); a[8] += p * f.x; a[9] += p * f.y;
            f = __half22float2(*(__half2*)&x1[j].y); a[10] += p * f.x; a[11] += p * f.y;
            f = __half22float2(*(__half2*)&x1[j].z); a[12] += p * f.x; a[13] += p * f.y;
            f = __half22float2(*(__half2*)&x1[j].w); a[14] += p * f.x; a[15] += p * f.y;
        }
    }
    if (e + 4 <= end) {
        int2 cc = g_cs[e + ql];
        float ll = g_al[cc.x * 8 + li];
        uint4 y0 = *(const uint4*)&g_xh[cc.x * 128 + li * 16];
        uint4 y1 = *(const uint4*)&g_xh[cc.x * 128 + li * 16 + 8];
        float aa = (ll + arn) * __int_as_float(cc.y);
        aa = (aa > 0.f) ? aa : 0.2f * aa;
        float p = exp2f(fminf(aa, 100.f));
        denom += p;
        float2 f;
        f = __half22float2(*(__half2*)&y0.x); a[0] += p * f.x; a[1] += p * f.y;
        f = __half22float2(*(__half2*)&y0.y); a[2] += p * f.x; a[3] += p * f.y;
        f = __half22float2(*(__half2*)&y0.z); a[4] += p * f.x; a[5] += p * f.y;
        f = __half22float2(*(__half2*)&y0.w); a[6] += p * f.x; a[7] += p * f.y;
        f = __half22float2(*(__half2*)&y1.x); a[8] += p * f.x; a[9] += p * f.y;
        f = __half22float2(*(__half2*)&y1.y); a[10] += p * f.x; a[11] += p * f.y;
        f = __half22float2(*(__half2*)&y1.z); a[12] += p * f.x; a[13] += p * f.y;
        f = __half22float2(*(__half2*)&y1.w); a[14] += p * f.x; a[15] += p * f.y;
        e += 4;
    }
    for (; e < end; e++) {
        int2 cc = g_cs[e];
        float ll = g_al[cc.x * 8 + li];
        uint4 y0 = *(const uint4*)&g_xh[cc.x * 128 + li * 16];
        uint4 y1 = *(const uint4*)&g_xh[cc.x * 128 + li * 16 + 8];
        float aa = (ll + arn) * __int_as_float(cc.y);
        aa = (aa > 0.f) ? aa : 0.2f * aa;
        float p = exp2f(fminf(aa, 100.f));
        if (ql) p = 0.f;
        denom += p;
        float2 f;
        f = __half22float2(*(__half2*)&y0.x); a[0] += p * f.x; a[1] += p * f.y;
        f = __half22float2(*(__half2*)&y0.y); a[2] += p * f.x; a[3] += p * f.y;
        f = __half22float2(*(__half2*)&y0.z); a[4] += p * f.x; a[5] += p * f.y;
        f = __half22float2(*(__half2*)&y0.w); a[6] += p * f.x; a[7] += p * f.y;
        f = __half22float2(*(__half2*)&y1.x); a[8] += p * f.x; a[9] += p * f.y;
        f = __half22float2(*(__half2*)&y1.y); a[10] += p * f.x; a[11] += p * f.y;
        f = __half22float2(*(__half2*)&y1.z); a[12] += p * f.x; a[13] += p * f.y;
        f = __half22float2(*(__half2*)&y1.w); a[14] += p * f.x; a[15] += p * f.y;
    }

    denom += __shfl_xor_sync(0xffffffffu, denom, 8);
    denom += __shfl_xor_sync(0xffffffffu, denom, 16);
#pragma unroll
    for (int k = 0; k < 16; k++) {
        a[k] += __shfl_xor_sync(0xffffffffu, a[k], 8);
        a[k] += __shfl_xor_sync(0xffffffffu, a[k], 16);
    }

    if (ql == 0) {
        float inv = (cnt0 > 0) ? (1.f / denom) : 0.f;
        int base = wid * 128 + li * 16;
#pragma unroll
        for (int q = 0; q < 4; q++) {
            float4 r = *(const float4*)&out[base + q * 4];
            float v0 = a[q * 4 + 0] * inv;
            float v1 = a[q * 4 + 1] * inv;
            float v2 = a[q * 4 + 2] * inv;
            float v3 = a[q * 4 + 3] * inv;
            r.x += (v0 > 0.f) ? v0 : (__expf(v0) - 1.f);
            r.y += (v1 > 0.f) ? v1 : (__expf(v1) - 1.f);
            r.z += (v2 > 0.f) ? v2 : (__expf(v2) - 1.f);
            r.w += (v3 > 0.f) ? v3 : (__expf(v3) - 1.f);
            *(float4*)&out[base + q * 4] = r;
        }
    }

    if (lane == 0)
        asm volatile("st.global.b32 [%0], %1;" :: "l"(&g_cnt[wid]), "r"(0));
}

// ---------------- launch ------------------------------------------------------
extern "C" void kernel_launch(void* const* d_in, const int* in_sizes, int n_in,
                              void* d_out, int out_size) {
    const float* feature = (const float*)d_in[0];
    const int*   esrc    = (const int*)d_in[1];
    const int*   edst    = (const int*)d_in[2];
    const float* ew      = (const float*)d_in[3];
    const float* wlin    = (const float*)d_in[4];
    const float* attl    = (const float*)d_in[5];
    const float* attr    = (const float*)d_in[6];
    const float* wres    = (const float*)d_in[7];
    int n = in_sizes[0] / 128;
    int e = in_sizes[1];
    float* out = (float*)d_out;

    cudaFuncSetAttribute(k_gemm, cudaFuncAttributeMaxDynamicSharedMemorySize,
                         GEMM_SMEM_BYTES);

    int e4 = (e + 3) / 4;
    k_scatter<<<(e4 + 255) / 256, 256>>>(esrc, edst, ew, e);

    int gb = ((n + 127) / 128) * 2;
    k_gemm<<<gb, 256, GEMM_SMEM_BYTES>>>(feature, wlin, wres, attl, attr, out, n);

    k_agg<<<(n * 32 + 255) / 256, 256>>>(out, n);
}